// round 5
// baseline (speedup 1.0000x reference)
#include <cuda_runtime.h>

#define B 8
#define E 2000
#define NT 10000
#define NRELS 25
#define KT 16
#define TT 3
#define LL 32

#define NBLK 148
#define NTHR 512
#define NTOT (NBLK * NTHR)        // 75776 threads
#define NWARP (NTOT / 32)         // 2368 warps

// ---------------- scratch (device globals; no allocs allowed) ----------------
__device__ int   g_heads[NT];
__device__ int   g_tails[NT];
__device__ int   g_rels[NT];
__device__ int   g_ent[B];
__device__ int   g_tidx[E];
__device__ float g_ebase[E * 24];        // hidden_base indicator [E][24]
__device__ float g_bflag[B * NRELS];     // hx_raw indicator [B][25]
__device__ float g_wp[TT * LL * NRELS];  // softmax(w[t]) [t][l][r]
__device__ float g_tanhw[LL];
__device__ float g_hidx[B * LL];         // hidden_x at t=0
__device__ float g_hidden[TT * E * LL];  // hidden gates [t][e][l]
__device__ float g_r0[E * B * LL];       // s buffers [e][b][l]
__device__ float g_r1[E * B * LL];
__device__ float g_r2[E * B * LL];

// grid barrier state (sense-reversing; gen monotonic, equality-compared)
__device__ int g_bar_count;
__device__ int g_bar_gen;

__device__ __forceinline__ float clip01(float x) { return fminf(fmaxf(x, 0.f), 1.f); }

__device__ __forceinline__ void grid_bar() {
    __syncthreads();
    if (threadIdx.x == 0) {
        int gen = *((volatile int*)&g_bar_gen);
        __threadfence();
        if (atomicAdd(&g_bar_count, 1) == NBLK - 1) {
            g_bar_count = 0;          // reset BEFORE release
            __threadfence();
            atomicAdd(&g_bar_gen, 1); // release
        } else {
            while (*((volatile int*)&g_bar_gen) == gen) { }
        }
        __threadfence();
    }
    __syncthreads();
}

__global__ void __launch_bounds__(NTHR, 1)
k_mega(const float* __restrict__ inx, const float* __restrict__ tmat,
       const float4* __restrict__ e2t, const float4* __restrict__ t2e,
       const float* __restrict__ t2r,
       const float* __restrict__ w, const float* __restrict__ weight,
       const float* __restrict__ h, const float* __restrict__ hx,
       const float* __restrict__ htype, const float* __restrict__ hxtype,
       const float* __restrict__ alpha, const float* __restrict__ beta,
       const float* __restrict__ alphax, const float* __restrict__ betax,
       float* __restrict__ out) {
    const int gtid = blockIdx.x * NTHR + threadIdx.x;
    const int W    = gtid >> 5;
    const int lane = threadIdx.x & 31;

    // ============ P1: zero scratch + 160MB extraction scan (HBM-bound) ============
    for (int i = gtid; i < E * B * LL; i += NTOT) { g_r0[i] = 0.f; g_r1[i] = 0.f; g_r2[i] = 0.f; }
    for (int i = gtid; i < E * 24;     i += NTOT) g_ebase[i] = 0.f;
    for (int i = gtid; i < B * NRELS;  i += NTOT) g_bflag[i] = 0.f;

    const int NE4 = E * NT / 4;   // 5M float4 per big matrix
    // e2triple [E][NT]: nonzero at (heads[n], n); NT%4==0 keeps float4 in-row
    for (int i = gtid; i < NE4; i += NTOT) {
        float4 v = e2t[i];
        if (v.x != 0.f || v.y != 0.f || v.z != 0.f || v.w != 0.f) {
            int idx = i * 4; int e = idx / NT; int n = idx - e * NT;
            if (v.x != 0.f) g_heads[n]     = e;
            if (v.y != 0.f) g_heads[n + 1] = e;
            if (v.z != 0.f) g_heads[n + 2] = e;
            if (v.w != 0.f) g_heads[n + 3] = e;
        }
    }
    // triple2e [NT][E]: nonzero at (n, tails[n]); E%4==0
    for (int i = gtid; i < NE4; i += NTOT) {
        float4 v = t2e[i];
        if (v.x != 0.f || v.y != 0.f || v.z != 0.f || v.w != 0.f) {
            int idx = i * 4; int n = idx / E; int e = idx - n * E;
            if (v.x != 0.f) g_tails[n] = e;
            if (v.y != 0.f) g_tails[n] = e + 1;
            if (v.z != 0.f) g_tails[n] = e + 2;
            if (v.w != 0.f) g_tails[n] = e + 3;
        }
    }
    for (int i = gtid; i < NT * NRELS; i += NTOT)
        if (t2r[i] != 0.f) g_rels[i / NRELS] = i % NRELS;
    for (int i = gtid; i < E * KT; i += NTOT)
        if (tmat[i] != 0.f) g_tidx[i / KT] = i % KT;
    for (int i = gtid; i < B * E; i += NTOT)
        if (inx[i] != 0.f) g_ent[i / E] = i % E;

    grid_bar();

    // ============ P2: indicator flags + softmax(w) + tanh(weight) ============
    for (int n = gtid; n < NT; n += NTOT) {
        int r = g_rels[n], tl = g_tails[n], hd = g_heads[n];
        if (r < NRELS - 1) g_ebase[tl * 24 + r] = 1.f;
#pragma unroll
        for (int b = 0; b < B; b++)
            if (hd == g_ent[b]) g_bflag[b * NRELS + r] = 1.f;
    }
    if (gtid < TT * LL) {       // softmax of w[t][l][:25]
        float vals[NRELS]; float m = -1e30f;
#pragma unroll
        for (int r = 0; r < NRELS; r++) { vals[r] = w[gtid * NRELS + r]; m = fmaxf(m, vals[r]); }
        float s = 0.f;
#pragma unroll
        for (int r = 0; r < NRELS; r++) { vals[r] = __expf(vals[r] - m); s += vals[r]; }
        float inv = __frcp_rn(s);
#pragma unroll
        for (int r = 0; r < NRELS; r++) g_wp[gtid * NRELS + r] = vals[r] * inv;
    }
    if (gtid >= 96 && gtid < 96 + LL) g_tanhw[gtid - 96] = tanhf(weight[gtid - 96]);

    grid_bar();

    // ============ P3: hidden gates + hidden_x(t=0) + prop0 ============
    for (int z = gtid; z < TT * E * LL; z += NTOT) {
        int l = z & 31; int rest = z >> 5; int e = rest % E; int t = rest / E;
        float a  = clip01(alpha[t * LL + l] * 0.1f);
        float bb = clip01(beta[t * LL + l] * 0.1f);
        int k = g_tidx[e];
        float htp = clip01(htype[(t * LL + l) * KT + k] * 0.1f);
        float acc = 0.f;
#pragma unroll
        for (int j = 0; j < 24; j++)
            acc += g_ebase[e * 24 + j] * clip01(h[(t * LL + l) * 24 + j] * 0.1f);
        g_hidden[(t * E + e) * LL + l] = clip01(a * htp + bb * acc) + (1.f - clip01(a + bb));
    }
    if (gtid < B * LL) {        // hidden_x at t=0 (only step where used)
        int b = gtid / LL, l = gtid % LL;
        float a0 = clip01(alpha[l] * 0.1f), b0 = clip01(beta[l] * 0.1f);
        int k = g_tidx[g_ent[b]];
        float htx = clip01(hxtype[l * KT + k] * 0.1f);
        float acc = 0.f;
#pragma unroll
        for (int j = 0; j < 24; j++) {
            int src = (j < 12) ? (j + 12) : (j - 12);  // concat(hx_raw[:,12:], hx_raw[:,:12])
            acc += g_bflag[b * NRELS + src] * clip01(hx[l * 24 + j] * 0.1f);
        }
        float gate = 1.f - clip01(clip01(alphax[l] * 0.1f) + clip01(betax[l] * 0.1f));
        g_hidx[gtid] = clip01(a0 * htx + b0 * acc) + gate;
    }
    {   // prop0: r0[tails[n]][b][lane] += wp0[lane][rels[n]] where heads[n]==ent[b]
        int entv[B];
#pragma unroll
        for (int b = 0; b < B; b++) entv[b] = g_ent[b];
        for (int n = W; n < NT; n += NWARP) {
            int hn = g_heads[n];
            bool any = false;
#pragma unroll
            for (int b = 0; b < B; b++) any |= (entv[b] == hn);
            if (!any) continue;
            int tl = g_tails[n];
            float wv = g_wp[lane * NRELS + g_rels[n]];
#pragma unroll
            for (int b = 0; b < B; b++)
                if (entv[b] == hn) atomicAdd(&g_r0[(tl * B + b) * LL + lane], wv);
        }
    }

    grid_bar();

    // ============ P4: prop step 1 (r0 -> r1); applies hidden0 * hidden_x, wp1 ====
    {
        float hxv[B];
#pragma unroll
        for (int b = 0; b < B; b++) hxv[b] = g_hidx[b * LL + lane];
        const float* wp1 = g_wp + 1 * LL * NRELS;
        for (int n = W; n < NT; n += NWARP) {
            int hn = g_heads[n];
            float hv = g_hidden[hn * LL + lane] * wp1[lane * NRELS + g_rels[n]];
            int tl = g_tails[n];
#pragma unroll
            for (int b = 0; b < B; b++) {
                float v = g_r0[(hn * B + b) * LL + lane];
                if (v != 0.f)
                    atomicAdd(&g_r1[(tl * B + b) * LL + lane], v * hv * hxv[b]);
            }
        }
    }

    grid_bar();

    // ============ P5: prop step 2 (r1 -> r2); applies hidden1, wp2 ============
    {
        const float* hid = g_hidden + 1 * E * LL;
        const float* wp2 = g_wp + 2 * LL * NRELS;
        for (int n = W; n < NT; n += NWARP) {
            int hn = g_heads[n];
            float hv = hid[hn * LL + lane] * wp2[lane * NRELS + g_rels[n]];
            int tl = g_tails[n];
#pragma unroll
            for (int b = 0; b < B; b++) {
                float v = g_r1[(hn * B + b) * LL + lane];
                if (v != 0.f)
                    atomicAdd(&g_r2[(tl * B + b) * LL + lane], v * hv);
            }
        }
    }

    grid_bar();

    // ============ P6: epilogue out[b][e] = sum_l r2 * hidden2 * tanh(weight) ====
    {
        const float* hid2 = g_hidden + 2 * E * LL;
        float tw = g_tanhw[lane];
        for (int idx = W; idx < B * E; idx += NWARP) {
            int e = idx % E, b = idx / E;
            float v = g_r2[(e * B + b) * LL + lane] * hid2[e * LL + lane] * tw;
#pragma unroll
            for (int o = 16; o > 0; o >>= 1) v += __shfl_down_sync(0xffffffffu, v, o);
            if (lane == 0) out[b * E + e] = v;
        }
    }
}

extern "C" void kernel_launch(void* const* d_in, const int* in_sizes, int n_in,
                              void* d_out, int out_size) {
    const float* inx    = (const float*)d_in[0];   // input_x   [8,2000]
    const float* tmat   = (const float*)d_in[1];   // type_mat  [2000,16]
    const float* e2t    = (const float*)d_in[2];   // e2triple  [2000,10000]
    const float* t2e    = (const float*)d_in[3];   // triple2e  [10000,2000]
    const float* t2r    = (const float*)d_in[4];   // triple2r  [10000,25]
    const float* w      = (const float*)d_in[5];   // [3,32,25]
    const float* weight = (const float*)d_in[6];   // [32,1]
    const float* h      = (const float*)d_in[7];   // [3,32,24]
    const float* hx     = (const float*)d_in[8];   // [32,24]
    const float* htype  = (const float*)d_in[9];   // [3,32,16]
    const float* hxtype = (const float*)d_in[10];  // [32,16]
    const float* alpha  = (const float*)d_in[11];  // [3,32]
    const float* beta   = (const float*)d_in[12];  // [3,32]
    const float* alphax = (const float*)d_in[13];  // [32]
    const float* betax  = (const float*)d_in[14];  // [32]
    float* out = (float*)d_out;

    k_mega<<<NBLK, NTHR>>>(inx, tmat, (const float4*)e2t, (const float4*)t2e, t2r,
                           w, weight, h, hx, htype, hxtype,
                           alpha, beta, alphax, betax, out);
}

// round 6
// speedup vs baseline: 1.2297x; 1.2297x over previous
#include <cuda_runtime.h>

#define B 8
#define E 2000
#define NT 10000
#define NRELS 25
#define KT 16
#define TT 3
#define LL 32

// tail persistent config: 1 CTA/SM guaranteed resident
#define TBLK 148
#define TTHR 512
#define TTOT (TBLK * TTHR)
#define TWARP (TTOT / 32)

// ---------------- scratch (device globals; no allocs allowed) ----------------
__device__ int   g_heads[NT];
__device__ int   g_tails[NT];
__device__ int   g_rels[NT];
__device__ int   g_ent[B];
__device__ int   g_tidx[E];
__device__ float g_ebase[E * 24];        // hidden_base indicator [E][24]
__device__ float g_bflag[B * NRELS];     // hx_raw indicator [B][25]
__device__ float g_wp[TT * LL * NRELS];  // softmax(w[t]) [t][l][r]
__device__ float g_tanhw[LL];
__device__ float g_hidx[B * LL];         // hidden_x at t=0
__device__ float g_hidden[TT * E * LL];  // hidden gates [t][e][l]
__device__ float g_r0[E * B * LL];       // s buffers [e][b][l]
__device__ float g_r1[E * B * LL];
__device__ float g_r2[E * B * LL];

// grid barrier state (sense-reversing; gen monotonic)
__device__ int g_bar_count;
__device__ int g_bar_gen;

__device__ __forceinline__ float clip01(float x) { return fminf(fmaxf(x, 0.f), 1.f); }

__device__ __forceinline__ void grid_bar() {
    __syncthreads();
    if (threadIdx.x == 0) {
        int gen = *((volatile int*)&g_bar_gen);
        __threadfence();
        if (atomicAdd(&g_bar_count, 1) == TBLK - 1) {
            g_bar_count = 0;
            __threadfence();
            atomicAdd(&g_bar_gen, 1);
        } else {
            while (*((volatile int*)&g_bar_gen) == gen) { }
        }
        __threadfence();
    }
    __syncthreads();
}

// ======== kernel 1: high-occupancy 160MB scan + scratch zeroing (HBM-bound) ========
__global__ void k_extract(const float* __restrict__ inx, const float* __restrict__ tmat,
                          const float4* __restrict__ e2t, const float4* __restrict__ t2e,
                          const float* __restrict__ t2r) {
    int st = gridDim.x * blockDim.x, i0 = blockIdx.x * blockDim.x + threadIdx.x;
    // zero scratch (disjoint from scan outputs)
    for (int i = i0; i < E * B * LL; i += st) { g_r0[i] = 0.f; g_r1[i] = 0.f; g_r2[i] = 0.f; }
    for (int i = i0; i < E * 24;     i += st) g_ebase[i] = 0.f;
    for (int i = i0; i < B * NRELS;  i += st) g_bflag[i] = 0.f;

    const int NE4 = E * NT / 4;   // 5M float4 per big matrix
    // e2triple [E][NT]: nonzero at (heads[n], n); NT%4==0 keeps float4 in-row
    for (int i = i0; i < NE4; i += st) {
        float4 v = __ldcs(&e2t[i]);                       // streaming: read-once
        if (v.x != 0.f || v.y != 0.f || v.z != 0.f || v.w != 0.f) {
            int idx = i * 4; int e = idx / NT; int n = idx - e * NT;
            if (v.x != 0.f) g_heads[n]     = e;
            if (v.y != 0.f) g_heads[n + 1] = e;
            if (v.z != 0.f) g_heads[n + 2] = e;
            if (v.w != 0.f) g_heads[n + 3] = e;
        }
    }
    // triple2e [NT][E]: nonzero at (n, tails[n]); E%4==0
    for (int i = i0; i < NE4; i += st) {
        float4 v = __ldcs(&t2e[i]);
        if (v.x != 0.f || v.y != 0.f || v.z != 0.f || v.w != 0.f) {
            int idx = i * 4; int n = idx / E; int e = idx - n * E;
            if (v.x != 0.f) g_tails[n] = e;
            if (v.y != 0.f) g_tails[n] = e + 1;
            if (v.z != 0.f) g_tails[n] = e + 2;
            if (v.w != 0.f) g_tails[n] = e + 3;
        }
    }
    for (int i = i0; i < NT * NRELS; i += st)
        if (__ldcs(&t2r[i]) != 0.f) g_rels[i / NRELS] = i % NRELS;
    for (int i = i0; i < E * KT; i += st)
        if (tmat[i] != 0.f) g_tidx[i / KT] = i % KT;
    for (int i = i0; i < B * E; i += st)
        if (inx[i] != 0.f) g_ent[i / E] = i % E;
}

// ======== kernel 2: persistent tail (latency-bound; everything else) ========
__global__ void __launch_bounds__(TTHR, 1)
k_tail(const float* __restrict__ w, const float* __restrict__ weight,
       const float* __restrict__ h, const float* __restrict__ hx,
       const float* __restrict__ htype, const float* __restrict__ hxtype,
       const float* __restrict__ alpha, const float* __restrict__ beta,
       const float* __restrict__ alphax, const float* __restrict__ betax,
       float* __restrict__ out) {
    const int gtid = blockIdx.x * TTHR + threadIdx.x;
    const int W    = gtid >> 5;
    const int lane = threadIdx.x & 31;

    // ---- A: indicator flags + softmax(w) + tanh(weight) ----
    for (int n = gtid; n < NT; n += TTOT) {
        int r = g_rels[n], tl = g_tails[n], hd = g_heads[n];
        if (r < NRELS - 1) g_ebase[tl * 24 + r] = 1.f;
#pragma unroll
        for (int b = 0; b < B; b++)
            if (hd == g_ent[b]) g_bflag[b * NRELS + r] = 1.f;
    }
    if (gtid < TT * LL) {       // softmax of w[t][l][:25]
        float vals[NRELS]; float m = -1e30f;
#pragma unroll
        for (int r = 0; r < NRELS; r++) { vals[r] = w[gtid * NRELS + r]; m = fmaxf(m, vals[r]); }
        float s = 0.f;
#pragma unroll
        for (int r = 0; r < NRELS; r++) { vals[r] = __expf(vals[r] - m); s += vals[r]; }
        float inv = __frcp_rn(s);
#pragma unroll
        for (int r = 0; r < NRELS; r++) g_wp[gtid * NRELS + r] = vals[r] * inv;
    }
    if (gtid >= 96 && gtid < 96 + LL) g_tanhw[gtid - 96] = tanhf(weight[gtid - 96]);

    grid_bar();

    // ---- B: hidden gates + hidden_x(t=0) + prop0 ----
    for (int z = gtid; z < TT * E * LL; z += TTOT) {
        int l = z & 31; int rest = z >> 5; int e = rest % E; int t = rest / E;
        float a  = clip01(alpha[t * LL + l] * 0.1f);
        float bb = clip01(beta[t * LL + l] * 0.1f);
        int k = g_tidx[e];
        float htp = clip01(htype[(t * LL + l) * KT + k] * 0.1f);
        float acc = 0.f;
#pragma unroll
        for (int j = 0; j < 24; j++)
            acc += g_ebase[e * 24 + j] * clip01(h[(t * LL + l) * 24 + j] * 0.1f);
        g_hidden[(t * E + e) * LL + l] = clip01(a * htp + bb * acc) + (1.f - clip01(a + bb));
    }
    if (gtid < B * LL) {        // hidden_x at t=0 (only step where used)
        int b = gtid / LL, l = gtid % LL;
        float a0 = clip01(alpha[l] * 0.1f), b0 = clip01(beta[l] * 0.1f);
        int k = g_tidx[g_ent[b]];
        float htx = clip01(hxtype[l * KT + k] * 0.1f);
        float acc = 0.f;
#pragma unroll
        for (int j = 0; j < 24; j++) {
            int src = (j < 12) ? (j + 12) : (j - 12);  // concat(hx_raw[:,12:], hx_raw[:,:12])
            acc += g_bflag[b * NRELS + src] * clip01(hx[l * 24 + j] * 0.1f);
        }
        float gate = 1.f - clip01(clip01(alphax[l] * 0.1f) + clip01(betax[l] * 0.1f));
        g_hidx[gtid] = clip01(a0 * htx + b0 * acc) + gate;
    }
    {   // prop0: r0[tails[n]][b][lane] += wp0[lane][rels[n]] where heads[n]==ent[b]
        int entv[B];
#pragma unroll
        for (int b = 0; b < B; b++) entv[b] = g_ent[b];
        for (int n = W; n < NT; n += TWARP) {
            int hn = g_heads[n];
            bool any = false;
#pragma unroll
            for (int b = 0; b < B; b++) any |= (entv[b] == hn);
            if (!any) continue;
            int tl = g_tails[n];
            float wv = g_wp[lane * NRELS + g_rels[n]];
#pragma unroll
            for (int b = 0; b < B; b++)
                if (entv[b] == hn) atomicAdd(&g_r0[(tl * B + b) * LL + lane], wv);
        }
    }

    grid_bar();

    // ---- C: prop step 1 (r0 -> r1); applies hidden0 * hidden_x, wp1 ----
    {
        float hxv[B];
#pragma unroll
        for (int b = 0; b < B; b++) hxv[b] = g_hidx[b * LL + lane];
        const float* wp1 = g_wp + 1 * LL * NRELS;
        for (int n = W; n < NT; n += TWARP) {
            int hn = g_heads[n];
            float hv = g_hidden[hn * LL + lane] * wp1[lane * NRELS + g_rels[n]];
            int tl = g_tails[n];
#pragma unroll
            for (int b = 0; b < B; b++) {
                float v = g_r0[(hn * B + b) * LL + lane];
                if (v != 0.f)
                    atomicAdd(&g_r1[(tl * B + b) * LL + lane], v * hv * hxv[b]);
            }
        }
    }

    grid_bar();

    // ---- D: prop step 2 (r1 -> r2); applies hidden1, wp2 ----
    {
        const float* hid = g_hidden + 1 * E * LL;
        const float* wp2 = g_wp + 2 * LL * NRELS;
        for (int n = W; n < NT; n += TWARP) {
            int hn = g_heads[n];
            float hv = hid[hn * LL + lane] * wp2[lane * NRELS + g_rels[n]];
            int tl = g_tails[n];
#pragma unroll
            for (int b = 0; b < B; b++) {
                float v = g_r1[(hn * B + b) * LL + lane];
                if (v != 0.f)
                    atomicAdd(&g_r2[(tl * B + b) * LL + lane], v * hv);
            }
        }
    }

    grid_bar();

    // ---- E: epilogue out[b][e] = sum_l r2 * hidden2 * tanh(weight) ----
    {
        const float* hid2 = g_hidden + 2 * E * LL;
        float tw = g_tanhw[lane];
        for (int idx = W; idx < B * E; idx += TWARP) {
            int e = idx % E, b = idx / E;
            float v = g_r2[(e * B + b) * LL + lane] * hid2[e * LL + lane] * tw;
#pragma unroll
            for (int o = 16; o > 0; o >>= 1) v += __shfl_down_sync(0xffffffffu, v, o);
            if (lane == 0) out[b * E + e] = v;
        }
    }
}

extern "C" void kernel_launch(void* const* d_in, const int* in_sizes, int n_in,
                              void* d_out, int out_size) {
    const float* inx    = (const float*)d_in[0];   // input_x   [8,2000]
    const float* tmat   = (const float*)d_in[1];   // type_mat  [2000,16]
    const float* e2t    = (const float*)d_in[2];   // e2triple  [2000,10000]
    const float* t2e    = (const float*)d_in[3];   // triple2e  [10000,2000]
    const float* t2r    = (const float*)d_in[4];   // triple2r  [10000,25]
    const float* w      = (const float*)d_in[5];   // [3,32,25]
    const float* weight = (const float*)d_in[6];   // [32,1]
    const float* h      = (const float*)d_in[7];   // [3,32,24]
    const float* hx     = (const float*)d_in[8];   // [32,24]
    const float* htype  = (const float*)d_in[9];   // [3,32,16]
    const float* hxtype = (const float*)d_in[10];  // [32,16]
    const float* alpha  = (const float*)d_in[11];  // [3,32]
    const float* beta   = (const float*)d_in[12];  // [3,32]
    const float* alphax = (const float*)d_in[13];  // [32]
    const float* betax  = (const float*)d_in[14];  // [32]
    float* out = (float*)d_out;

    k_extract<<<2048, 256>>>(inx, tmat, (const float4*)e2t, (const float4*)t2e, t2r);
    k_tail<<<TBLK, TTHR>>>(w, weight, h, hx, htype, hxtype,
                           alpha, beta, alphax, betax, out);
}

// round 11
// speedup vs baseline: 1.9400x; 1.5777x over previous
#include <cuda_runtime.h>

#define B 8
#define E 2000
#define NT 10000
#define NRELS 25
#define KT 16
#define TT 3
#define LL 32

// ---------------- scratch (device globals; no allocs allowed) ----------------
__device__ int   g_heads[NT];
__device__ int   g_tails[NT];
__device__ int   g_rels[NT];
__device__ int   g_ent[B];
__device__ int   g_tidx[E];
__device__ int   g_emask[E];             // bit r set iff exists triple tail=e, rel=r (r<24)
__device__ int   g_bmask[B];             // bit r set iff exists triple head=ent[b], rel=r
__device__ float g_wp[TT * LL * NRELS];  // softmax(w[t]) [t][l][r]
__device__ float g_tanhw[LL];
__device__ float g_hidx[B * LL];         // hidden_x at t=0
__device__ float g_hidden[TT * E * LL];  // hidden gates [t][e][l]
__device__ float g_r0[E * B * LL];       // s buffers [e][b][l]
__device__ float g_r1[E * B * LL];
__device__ float g_r2[E * B * LL];

__device__ __forceinline__ float clip01(float x) { return fminf(fmaxf(x, 0.f), 1.f); }

// ======== K1: high-occupancy 160MB streaming scan + scratch zeroing ========
__global__ void k_extract(const float* __restrict__ inx, const float* __restrict__ tmat,
                          const float4* __restrict__ e2t, const float4* __restrict__ t2e,
                          const float* __restrict__ t2r) {
    int st = gridDim.x * blockDim.x, i0 = blockIdx.x * blockDim.x + threadIdx.x;
    // zero scratch (disjoint from scan outputs)
    for (int i = i0; i < E * B * LL; i += st) { g_r0[i] = 0.f; g_r1[i] = 0.f; g_r2[i] = 0.f; }
    for (int i = i0; i < E; i += st) g_emask[i] = 0;
    if (i0 < B) g_bmask[i0] = 0;

    const int NE4 = E * NT / 4;   // 5M float4 per big matrix
    // e2triple [E][NT]: nonzero at (heads[n], n); NT%4==0 keeps float4 in-row
    for (int i = i0; i < NE4; i += st) {
        float4 v = __ldcs(&e2t[i]);                       // streaming: read-once
        if (v.x != 0.f || v.y != 0.f || v.z != 0.f || v.w != 0.f) {
            int idx = i * 4; int e = idx / NT; int n = idx - e * NT;
            if (v.x != 0.f) g_heads[n]     = e;
            if (v.y != 0.f) g_heads[n + 1] = e;
            if (v.z != 0.f) g_heads[n + 2] = e;
            if (v.w != 0.f) g_heads[n + 3] = e;
        }
    }
    // triple2e [NT][E]: nonzero at (n, tails[n]); E%4==0
    for (int i = i0; i < NE4; i += st) {
        float4 v = __ldcs(&t2e[i]);
        if (v.x != 0.f || v.y != 0.f || v.z != 0.f || v.w != 0.f) {
            int idx = i * 4; int n = idx / E; int e = idx - n * E;
            if (v.x != 0.f) g_tails[n] = e;
            if (v.y != 0.f) g_tails[n] = e + 1;
            if (v.z != 0.f) g_tails[n] = e + 2;
            if (v.w != 0.f) g_tails[n] = e + 3;
        }
    }
    for (int i = i0; i < NT * NRELS; i += st)
        if (__ldcs(&t2r[i]) != 0.f) g_rels[i / NRELS] = i % NRELS;
    for (int i = i0; i < E * KT; i += st)
        if (tmat[i] != 0.f) g_tidx[i / KT] = i % KT;
    for (int i = i0; i < B * E; i += st)
        if (inx[i] != 0.f) g_ent[i / E] = i % E;
}

// ======== K2: indicator bitmasks + softmax(w) + tanh(weight) ========
// blocks [0,40): flags over triples; block 40: softmax + tanh
__global__ void k_flags(const float* __restrict__ w, const float* __restrict__ weight) {
    if (blockIdx.x < 40) {
        int n = blockIdx.x * 256 + threadIdx.x;
        if (n >= NT) return;
        int r = g_rels[n], tl = g_tails[n], hd = g_heads[n];
        if (r < NRELS - 1) atomicOr(&g_emask[tl], 1 << r);
        int e0 = g_ent[0], e1 = g_ent[1], e2 = g_ent[2], e3 = g_ent[3];
        int e4 = g_ent[4], e5 = g_ent[5], e6 = g_ent[6], e7 = g_ent[7];
        int bit = 1 << r;
        if (hd == e0) atomicOr(&g_bmask[0], bit);
        if (hd == e1) atomicOr(&g_bmask[1], bit);
        if (hd == e2) atomicOr(&g_bmask[2], bit);
        if (hd == e3) atomicOr(&g_bmask[3], bit);
        if (hd == e4) atomicOr(&g_bmask[4], bit);
        if (hd == e5) atomicOr(&g_bmask[5], bit);
        if (hd == e6) atomicOr(&g_bmask[6], bit);
        if (hd == e7) atomicOr(&g_bmask[7], bit);
        return;
    }
    int i = threadIdx.x;
    if (i < TT * LL) {          // softmax of w[t][l][:25]
        float vals[NRELS]; float m = -1e30f;
#pragma unroll
        for (int r = 0; r < NRELS; r++) { vals[r] = w[i * NRELS + r]; m = fmaxf(m, vals[r]); }
        float s = 0.f;
#pragma unroll
        for (int r = 0; r < NRELS; r++) { vals[r] = __expf(vals[r] - m); s += vals[r]; }
        float inv = __frcp_rn(s);
#pragma unroll
        for (int r = 0; r < NRELS; r++) g_wp[i * NRELS + r] = vals[r] * inv;
    }
    if (i >= 96 && i < 96 + LL) g_tanhw[i - 96] = tanhf(weight[i - 96]);
}

// ======== K3: hidden gates + hidden_x(t=0) + prop0 (independent outputs) ========
// blocks [0,750): hidden[t][e][l]; block 750: hidden_x; blocks [751,751+1250): prop0
__global__ void k_gates(const float* __restrict__ h, const float* __restrict__ htype,
                        const float* __restrict__ alpha, const float* __restrict__ beta,
                        const float* __restrict__ hx, const float* __restrict__ hxtype,
                        const float* __restrict__ alphax, const float* __restrict__ betax) {
    if (blockIdx.x < 750) {
        int z = blockIdx.x * 256 + threadIdx.x;       // z < 192000 = TT*E*LL exactly
        int l = z & 31; int rest = z >> 5; int e = rest % E; int t = rest / E;
        float a  = clip01(alpha[t * LL + l] * 0.1f);
        float bb = clip01(beta[t * LL + l] * 0.1f);
        int k = g_tidx[e];
        float htp = clip01(htype[(t * LL + l) * KT + k] * 0.1f);
        int mask = g_emask[e];
        float acc = 0.f;
#pragma unroll
        for (int j = 0; j < 24; j++)
            if (mask & (1 << j)) acc += clip01(h[(t * LL + l) * 24 + j] * 0.1f);
        g_hidden[(t * E + e) * LL + l] = clip01(a * htp + bb * acc) + (1.f - clip01(a + bb));
        return;
    }
    if (blockIdx.x == 750) {    // hidden_x at t=0 (256 threads = B*LL)
        int i = threadIdx.x;
        int b = i / LL, l = i % LL;
        float a0 = clip01(alpha[l] * 0.1f), b0 = clip01(beta[l] * 0.1f);
        int k = g_tidx[g_ent[b]];
        float htx = clip01(hxtype[l * KT + k] * 0.1f);
        int mask = g_bmask[b];
        float acc = 0.f;
#pragma unroll
        for (int j = 0; j < 24; j++) {
            int src = (j < 12) ? (j + 12) : (j - 12);  // concat(hx_raw[:,12:24], hx_raw[:,:12])
            if (mask & (1 << src)) acc += clip01(hx[l * 24 + j] * 0.1f);
        }
        float gate = 1.f - clip01(clip01(alphax[l] * 0.1f) + clip01(betax[l] * 0.1f));
        g_hidx[i] = clip01(a0 * htx + b0 * acc) + gate;
        return;
    }
    // prop0: warp per triple. r0[tails[n]][b][lane] += wp0[lane][rels[n]] if heads[n]==ent[b]
    int n = (blockIdx.x - 751) * 8 + (threadIdx.x >> 5);
    if (n >= NT) return;
    int lane = threadIdx.x & 31;
    int hn = g_heads[n];
    int entv[B];
#pragma unroll
    for (int b = 0; b < B; b++) entv[b] = g_ent[b];
    bool hit = false;
#pragma unroll
    for (int b = 0; b < B; b++) hit |= (entv[b] == hn);
    if (!hit) return;
    int tl = g_tails[n];
    float wv = g_wp[lane * NRELS + g_rels[n]];
#pragma unroll
    for (int b = 0; b < B; b++)
        if (entv[b] == hn) atomicAdd(&g_r0[(tl * B + b) * LL + lane], wv);
}

// ======== K4/K5: propagation; previous step's hidden (+hidx at step1) applied at read ====
template <int STEP>
__global__ void k_prop() {
    int n = blockIdx.x * 8 + (threadIdx.x >> 5);
    if (n >= NT) return;
    int lane = threadIdx.x & 31;
    const float* src = (STEP == 1) ? g_r0 : g_r1;
    float*       dst = (STEP == 1) ? g_r1 : g_r2;
    int hn = g_heads[n], tl = g_tails[n], r = g_rels[n];
    float hv = g_hidden[((STEP - 1) * E + hn) * LL + lane]
             * g_wp[(STEP * LL + lane) * NRELS + r];
    float v[B];
#pragma unroll
    for (int b = 0; b < B; b++) v[b] = src[(hn * B + b) * LL + lane];  // 8 independent loads
#pragma unroll
    for (int b = 0; b < B; b++) {
        if (v[b] != 0.f) {
            float x = v[b] * hv;
            if (STEP == 1) x *= g_hidx[b * LL + lane];
            atomicAdd(&dst[(tl * B + b) * LL + lane], x);
        }
    }
}

// ======== K6: epilogue out[b][e] = sum_l r2 * hidden2 * tanh(weight) ========
__global__ void k_out(float* __restrict__ out) {
    int idx = blockIdx.x * 8 + (threadIdx.x >> 5);   // warp per (b,e)
    if (idx >= B * E) return;
    int lane = threadIdx.x & 31;
    int e = idx % E, b = idx / E;
    float v = g_r2[(e * B + b) * LL + lane] * g_hidden[(2 * E + e) * LL + lane] * g_tanhw[lane];
#pragma unroll
    for (int o = 16; o > 0; o >>= 1) v += __shfl_down_sync(0xffffffffu, v, o);
    if (lane == 0) out[b * E + e] = v;
}

extern "C" void kernel_launch(void* const* d_in, const int* in_sizes, int n_in,
                              void* d_out, int out_size) {
    const float* inx    = (const float*)d_in[0];   // input_x   [8,2000]
    const float* tmat   = (const float*)d_in[1];   // type_mat  [2000,16]
    const float* e2t    = (const float*)d_in[2];   // e2triple  [2000,10000]
    const float* t2e    = (const float*)d_in[3];   // triple2e  [10000,2000]
    const float* t2r    = (const float*)d_in[4];   // triple2r  [10000,25]
    const float* w      = (const float*)d_in[5];   // [3,32,25]
    const float* weight = (const float*)d_in[6];   // [32,1]
    const float* h      = (const float*)d_in[7];   // [3,32,24]
    const float* hx     = (const float*)d_in[8];   // [32,24]
    const float* htype  = (const float*)d_in[9];   // [3,32,16]
    const float* hxtype = (const float*)d_in[10];  // [32,16]
    const float* alpha  = (const float*)d_in[11];  // [3,32]
    const float* beta   = (const float*)d_in[12];  // [3,32]
    const float* alphax = (const float*)d_in[13];  // [32]
    const float* betax  = (const float*)d_in[14];  // [32]
    float* out = (float*)d_out;

    k_extract<<<2048, 256>>>(inx, tmat, (const float4*)e2t, (const float4*)t2e, t2r);
    k_flags<<<41, 256>>>(w, weight);
    k_gates<<<751 + 1250, 256>>>(h, htype, alpha, beta, hx, hxtype, alphax, betax);
    k_prop<1><<<1250, 256>>>();   // r0 -> r1: hidden0 * hidden_x, wp1
    k_prop<2><<<1250, 256>>>();   // r1 -> r2: hidden1, wp2
    k_out<<<2000, 256>>>(out);
}